// round 1
// baseline (speedup 1.0000x reference)
#include <cuda_runtime.h>
#include <cuda_bf16.h>
#include <math.h>

#define B_ROWS 2048
#define C_COLS 32000
#define TPB 256

__device__ float g_row_loss[B_ROWS];

// Asymptotic/exact harmonic number H(n), n >= 0. H(0) = 0.
__device__ __forceinline__ float harmonic(int n) {
    if (n <= 0) return 0.0f;
    if (n < 32) {
        float h = 0.0f;
        #pragma unroll 1
        for (int i = 1; i <= n; ++i) h += 1.0f / (float)i;
        return h;
    }
    const float gamma = 0.57721566490153286f;
    float x = (float)n;
    float inv = 1.0f / x;
    float inv2 = inv * inv;
    return logf(x) + gamma + 0.5f * inv - (1.0f / 12.0f) * inv2
           + (1.0f / 120.0f) * inv2 * inv2;
}

__global__ void __launch_bounds__(TPB) row_kernel(const float* __restrict__ scores,
                                                  const int* __restrict__ targets) {
    int b = blockIdx.x;
    const float* row = scores + (size_t)b * C_COLS;
    int t = targets[b];
    float gt = __ldg(row + t);   // same address across threads -> broadcast

    const float4* row4 = reinterpret_cast<const float4*>(row);
    const int n4 = C_COLS / 4;   // 8000

    float hs = 0.0f;
    int cnt = 0;
    for (int i = threadIdx.x; i < n4; i += TPB) {
        float4 v = row4[i];
        cnt += (v.x > gt) + (v.y > gt) + (v.z > gt) + (v.w > gt);
        hs += fmaxf(v.x - gt + 1.0f, 0.0f);
        hs += fmaxf(v.y - gt + 1.0f, 0.0f);
        hs += fmaxf(v.z - gt + 1.0f, 0.0f);
        hs += fmaxf(v.w - gt + 1.0f, 0.0f);
    }

    // warp reduce
    #pragma unroll
    for (int off = 16; off > 0; off >>= 1) {
        hs  += __shfl_down_sync(0xFFFFFFFFu, hs,  off);
        cnt += __shfl_down_sync(0xFFFFFFFFu, cnt, off);
    }

    __shared__ float s_hs[TPB / 32];
    __shared__ int   s_cnt[TPB / 32];
    int wid = threadIdx.x >> 5;
    int lid = threadIdx.x & 31;
    if (lid == 0) { s_hs[wid] = hs; s_cnt[wid] = cnt; }
    __syncthreads();

    if (threadIdx.x == 0) {
        float hsum = 0.0f;
        int   csum = 0;
        #pragma unroll
        for (int w = 0; w < TPB / 32; ++w) { hsum += s_hs[w]; csum += s_cnt[w]; }
        // target itself contributed relu(1 + gt - gt) = 1 to hsum; remove it.
        float hinge = hsum - 1.0f;
        int rank = csum;                 // #(scores > gt); target not counted (gt !> gt)
        float weight = (rank == 0) ? 0.0f : harmonic(rank) / (float)rank;
        g_row_loss[b] = weight * hinge;
    }
}

__global__ void __launch_bounds__(256) reduce_kernel(float* __restrict__ out) {
    __shared__ float s[256];
    float acc = 0.0f;
    #pragma unroll
    for (int i = threadIdx.x; i < B_ROWS; i += 256) acc += g_row_loss[i];
    s[threadIdx.x] = acc;
    __syncthreads();
    #pragma unroll
    for (int off = 128; off > 0; off >>= 1) {
        if (threadIdx.x < off) s[threadIdx.x] += s[threadIdx.x + off];
        __syncthreads();
    }
    if (threadIdx.x == 0) out[0] = s[0] / (float)B_ROWS;
}

extern "C" void kernel_launch(void* const* d_in, const int* in_sizes, int n_in,
                              void* d_out, int out_size) {
    const float* scores  = (const float*)d_in[0];
    const int*   targets = (const int*)d_in[1];
    float* out = (float*)d_out;

    row_kernel<<<B_ROWS, TPB>>>(scores, targets);
    reduce_kernel<<<1, 256>>>(out);
}